// round 5
// baseline (speedup 1.0000x reference)
#include <cuda_runtime.h>
#include <cuda_bf16.h>

// scatter_mean: out[m, c] = sum_{i: idx[i]==m} in[i, c] / max(count_m, 1)
// N = 4,000,000 rows, C = 16 channels fp32, M = 500,000 segments, idx int32.
//
// HW model: scatter is bound by per-SM REDG issue at ~1.29 cyc/lane (spread),
// 16B/lane max (red.v4.f32) -> 16M lanes -> ~77 us floor. Surrounding passes
// are the remaining slack: zero via HW memset, finalize tuned for MLP.

#define CHANNELS 16
#define MAX_SEGMENTS 500000

// Scratch: per-segment counts (allocation-free rule -> __device__ global).
__device__ float g_counts[MAX_SEGMENTS];

// ---------------------------------------------------------------------------
// Scatter-add, 4 lanes per row (quad-per-row).
// Each lane: 1 float4 load + 1 red.global.add.v4.f32 (16B). Quad lanes cover
// one 64B destination row. Lane 0 of each quad adds the count.
// ---------------------------------------------------------------------------
__global__ void __launch_bounds__(256, 8)
dve_scatter_kernel(const float4* __restrict__ in,
                   const int* __restrict__ idx,
                   float4* __restrict__ sums4,
                   int n) {
    int t = blockIdx.x * blockDim.x + threadIdx.x;   // [0, 4n)
    int row = t >> 2;
    int q = t & 3;
    if (row >= n) return;

    int s = __ldg(idx + row);                         // quad lanes share a sector
    float4 v = __ldg(in + (size_t)row * 4 + q);       // warp reads 8 rows = 512B

    float4* p = sums4 + (size_t)s * 4 + q;            // quad covers one 64B row
    asm volatile("red.global.add.v4.f32 [%0], {%1, %2, %3, %4};"
                 :: "l"(p), "f"(v.x), "f"(v.y), "f"(v.z), "f"(v.w) : "memory");

    if (q == 0)
        atomicAdd(&g_counts[s], 1.0f);
}

// ---------------------------------------------------------------------------
// Finalize: divide sums by max(count, 1). Two segments per thread for MLP
// (independent count + 4x float4 loads in flight before any store).
// ---------------------------------------------------------------------------
__global__ void __launch_bounds__(256, 8)
dve_finalize_kernel(float4* __restrict__ out, int m) {
    int base = (blockIdx.x * blockDim.x + threadIdx.x) * 2;

#pragma unroll
    for (int r = 0; r < 2; r++) {
        int i = base + r;
        if (i >= m) break;

        float inv = 1.0f / fmaxf(g_counts[i], 1.0f);
        float4* row = out + (size_t)i * 4;

        float4 v0 = row[0];
        float4 v1 = row[1];
        float4 v2 = row[2];
        float4 v3 = row[3];
        v0.x *= inv; v0.y *= inv; v0.z *= inv; v0.w *= inv;
        v1.x *= inv; v1.y *= inv; v1.z *= inv; v1.w *= inv;
        v2.x *= inv; v2.y *= inv; v2.z *= inv; v2.w *= inv;
        v3.x *= inv; v3.y *= inv; v3.z *= inv; v3.w *= inv;
        row[0] = v0;
        row[1] = v1;
        row[2] = v2;
        row[3] = v3;
    }
}

// ---------------------------------------------------------------------------
// Launch
// ---------------------------------------------------------------------------
extern "C" void kernel_launch(void* const* d_in, const int* in_sizes, int n_in,
                              void* d_out, int out_size) {
    const float4* in = (const float4*)d_in[0];   // [N, 16] fp32
    const int* idx = (const int*)d_in[1];        // [N] int32
    float* out = (float*)d_out;                  // [M, 16] fp32

    int n = in_sizes[0] / CHANNELS;   // 4,000,000
    int m = out_size / CHANNELS;      // 500,000

    // Zero sums + counts via HW memset nodes (graph-capturable, no alloc).
    void* counts_ptr = nullptr;
    cudaGetSymbolAddress(&counts_ptr, g_counts);
    cudaMemsetAsync(d_out, 0, (size_t)out_size * sizeof(float), 0);
    cudaMemsetAsync(counts_ptr, 0, (size_t)m * sizeof(float), 0);

    {
        int threads = 256;
        long long total = (long long)n * 4;
        int blocks = (int)((total + threads - 1) / threads);
        dve_scatter_kernel<<<blocks, threads>>>(in, idx, (float4*)out, n);
    }
    {
        int threads = 256;
        int per_block = threads * 2;
        int blocks = (m + per_block - 1) / per_block;
        dve_finalize_kernel<<<blocks, threads>>>((float4*)out, m);
    }
}

// round 6
// speedup vs baseline: 1.1300x; 1.1300x over previous
#include <cuda_runtime.h>
#include <cuda_bf16.h>

// scatter_mean: out[m, c] = sum_{i: idx[i]==m} in[i, c] / max(count_m, 1)
// N = 4,000,000 rows, C = 16 channels fp32, M = 500,000 segments, idx int32.
//
// HW model: scatter bound by per-lane REDG issue (~77 us floor at 16B/lane).
// Memsets ~7 us (HW fill). Finalize is pure bandwidth (66 MB -> ~13 us) if
// given enough threads; R5 showed starving it of threads costs 2x.

#define CHANNELS 16
#define MAX_SEGMENTS 500000

// Scratch: per-segment counts (allocation-free rule -> __device__ global).
__device__ float g_counts[MAX_SEGMENTS];

// ---------------------------------------------------------------------------
// Scatter-add, 4 lanes per row (quad-per-row).
// Each lane: 1 float4 load + 1 red.global.add.v4.f32 (16B). Quad lanes cover
// one 64B destination row. Lane 0 of each quad adds the count.
// ---------------------------------------------------------------------------
__global__ void __launch_bounds__(256, 8)
dve_scatter_kernel(const float4* __restrict__ in,
                   const int* __restrict__ idx,
                   float4* __restrict__ sums4,
                   int n) {
    int t = blockIdx.x * blockDim.x + threadIdx.x;   // [0, 4n)
    int row = t >> 2;
    int q = t & 3;
    if (row >= n) return;

    int s = __ldg(idx + row);                         // quad lanes share a sector
    float4 v = __ldg(in + (size_t)row * 4 + q);       // warp reads 8 rows = 512B

    float4* p = sums4 + (size_t)s * 4 + q;            // quad covers one 64B row
    asm volatile("red.global.add.v4.f32 [%0], {%1, %2, %3, %4};"
                 :: "l"(p), "f"(v.x), "f"(v.y), "f"(v.z), "f"(v.w) : "memory");

    if (q == 0)
        atomicAdd(&g_counts[s], 1.0f);
}

// ---------------------------------------------------------------------------
// Finalize: one float4 per thread (4 threads per segment). Fully coalesced
// load/store; count load dedups across the quad in L1. 8M threads hide all
// latency -> pure-bandwidth pass.
// ---------------------------------------------------------------------------
__global__ void __launch_bounds__(256, 8)
dve_finalize_kernel(float4* __restrict__ out, int total4) {
    int t = blockIdx.x * blockDim.x + threadIdx.x;   // [0, m*4)
    if (t >= total4) return;

    int seg = t >> 2;
    float inv = 1.0f / fmaxf(g_counts[seg], 1.0f);

    float4 v = out[t];
    v.x *= inv; v.y *= inv; v.z *= inv; v.w *= inv;
    out[t] = v;
}

// ---------------------------------------------------------------------------
// Launch
// ---------------------------------------------------------------------------
extern "C" void kernel_launch(void* const* d_in, const int* in_sizes, int n_in,
                              void* d_out, int out_size) {
    const float4* in = (const float4*)d_in[0];   // [N, 16] fp32
    const int* idx = (const int*)d_in[1];        // [N] int32
    float* out = (float*)d_out;                  // [M, 16] fp32

    int n = in_sizes[0] / CHANNELS;   // 4,000,000
    int m = out_size / CHANNELS;      // 500,000

    // Zero sums + counts via HW memset nodes (graph-capturable, no alloc).
    void* counts_ptr = nullptr;
    cudaGetSymbolAddress(&counts_ptr, g_counts);
    cudaMemsetAsync(d_out, 0, (size_t)out_size * sizeof(float), 0);
    cudaMemsetAsync(counts_ptr, 0, (size_t)m * sizeof(float), 0);

    {
        int threads = 256;
        long long total = (long long)n * 4;
        int blocks = (int)((total + threads - 1) / threads);
        dve_scatter_kernel<<<blocks, threads>>>(in, idx, (float4*)out, n);
    }
    {
        int threads = 256;
        int total4 = m * 4;                       // 2,000,000 float4s
        int blocks = (total4 + threads - 1) / threads;
        dve_finalize_kernel<<<blocks, threads>>>((float4*)out, total4);
    }
}